// round 14
// baseline (speedup 1.0000x reference)
#include <cuda_runtime.h>
#include <cstdint>

#define BB 64
#define NN 512
#define DD 64
#define HH 4
#define CC 64
#define NEGS 0.2f

// Scratch (device globals - no runtime allocation allowed)
__device__ float g_h[BB*HH*NN*CC];          // [b][h][n][c]  (head-major slabs)
__device__ float g_x[BB*NN*DD];             // layer activations
__device__ float g_asrc[BB*HH*NN];          // [b][h][n]
__device__ float g_adst[BB*HH*NN];          // [b][h][n]
__device__ float g_S1f[BB*HH*520*CC];       // full suffix sums (h-space)
__device__ float g_P2f[BB*HH*520*CC];       // full prefix sums (h-space)
__device__ float g_r1[BB*HH*NN];            // 0.25*e^{d}/den per i
__device__ float g_r2[BB*HH*NN];            // 0.25*e^{.2d}/den per i
__device__ int   g_k[BB*HH*NN];             // split index per i

// ---------------------------------------------------------------------------
// k_lin (v2, scalar 8x8): h = x @ W^T.
// Tile: 128 rows x 128 cols (2 heads), 256 threads, microtile 8i x 8c.
// LDS: 64 B per 64 FMA (1 FMA/B) -> FMA-bound, not crossbar-bound.
// Epilogue: h -> g_h[b][h][n][c] slab + a_src/a_dst via 8-lane shfl reduce.
// dyn smem: s_x[64][136] + s_w[64][136] = 69632 B
// ---------------------------------------------------------------------------
extern __shared__ float linsm[];

__global__ __launch_bounds__(256, 2) void k_lin(
    const float* __restrict__ x, const float* __restrict__ W,
    const float* __restrict__ attS, const float* __restrict__ attD)
{
    float (*s_x)[136] = (float(*)[136])linsm;              // [k][row 0..127]
    float (*s_w)[136] = (float(*)[136])(linsm + 64 * 136); // [k][2-head col 0..127]
    const int t    = threadIdx.x;
    const int row0 = blockIdx.x * 128;
    const int hp   = blockIdx.y;            // head pair (0: h0/h1, 1: h2/h3)

    // stage x and W transposed: thread covers row/col r = t&127, k-half kh
    {
        const int r  = t & 127;
        const int kh = t >> 7;              // 0/1 -> k 0..31 / 32..63
        const float4* xs = (const float4*)x + (size_t)(row0 + r) * 16 + kh * 8;
        const int hh = hp * 2 + (r >> 6);   // W row's head
        const int cl = r & 63;
        const float4* ws = (const float4*)W + (size_t)(hh * 64 + cl) * 16 + kh * 8;
        #pragma unroll
        for (int j4 = 0; j4 < 8; j4++) {
            float4 v = xs[j4];
            int k0 = kh * 32 + j4 * 4;
            s_x[k0+0][r] = v.x; s_x[k0+1][r] = v.y;
            s_x[k0+2][r] = v.z; s_x[k0+3][r] = v.w;
            float4 u = ws[j4];
            s_w[k0+0][r] = u.x; s_w[k0+1][r] = u.y;
            s_w[k0+2][r] = u.z; s_w[k0+3][r] = u.w;
        }
    }
    __syncthreads();

    const int tx = t & 15;   // c group (8 cols within 128)
    const int ty = t >> 4;   // i group (8 rows within 128)
    float acc[8][8] = {};

    #pragma unroll 2
    for (int k = 0; k < 64; k++) {
        float4 a0 = *(const float4*)&s_x[k][ty * 8];
        float4 a1 = *(const float4*)&s_x[k][ty * 8 + 4];
        float4 b0 = *(const float4*)&s_w[k][tx * 8];
        float4 b1 = *(const float4*)&s_w[k][tx * 8 + 4];
        float av[8] = {a0.x, a0.y, a0.z, a0.w, a1.x, a1.y, a1.z, a1.w};
        float bv[8] = {b0.x, b0.y, b0.z, b0.w, b1.x, b1.y, b1.z, b1.w};
        #pragma unroll
        for (int i = 0; i < 8; i++)
            #pragma unroll
            for (int c = 0; c < 8; c++)
                acc[i][c] += av[i] * bv[c];
    }

    // epilogue
    const int hh = hp * 2 + (tx >> 3);      // this thread's head
    const int c0 = (tx & 7) * 8;            // col offset within head
    float aSv[8], aDv[8];
    #pragma unroll
    for (int c = 0; c < 8; c++) {
        aSv[c] = attS[hh * 64 + c0 + c];
        aDv[c] = attD[hh * 64 + c0 + c];
    }
    #pragma unroll
    for (int i = 0; i < 8; i++) {
        int ng = row0 + ty * 8 + i;
        int b = ng >> 9, n = ng & 511;
        float* hpr = g_h + ((size_t)(b * HH + hh) * NN + n) * CC + c0;
        *(float4*)hpr       = make_float4(acc[i][0], acc[i][1], acc[i][2], acc[i][3]);
        *(float4*)(hpr + 4) = make_float4(acc[i][4], acc[i][5], acc[i][6], acc[i][7]);

        float ps = 0.f, pd = 0.f;
        #pragma unroll
        for (int c = 0; c < 8; c++) { ps += acc[i][c] * aSv[c]; pd += acc[i][c] * aDv[c]; }
        // reduce across the 8 lanes sharing (ty, head): offsets 1,2,4
        #pragma unroll
        for (int off = 4; off > 0; off >>= 1) {
            ps += __shfl_xor_sync(0xffffffffu, ps, off);
            pd += __shfl_xor_sync(0xffffffffu, pd, off);
        }
        if ((tx & 7) == 0) {
            g_asrc[(b * HH + hh) * NN + n] = ps;
            g_adst[(b * HH + hh) * NN + n] = pd;
        }
    }
}

// ---------------------------------------------------------------------------
// k_prep (R12/R13-proven), 512 threads, one block per (b,h).
// ---------------------------------------------------------------------------
extern __shared__ float psm[];

__global__ __launch_bounds__(512) void k_prep()
{
    float* s_s  = psm;              // 512
    float* s_dd = psm + 512;
    float* s_W1 = psm + 1024;
    float* s_W2 = psm + 1536;
    int*   s_pj = (int*)(psm + 2048);
    float* CH1  = psm + 2560;       // [66][64]
    float* CH2  = psm + 6784;       // [66][64]
    float* CH1d = psm + 11008;      // [66]
    float* CH2d = psm + 11074;      // [66]
    float* s1d  = psm + 11140;      // [520]
    float* p2d  = psm + 11660;      // [520]  -> 12180 floats

    const int t = threadIdx.x;
    const int b = blockIdx.x;
    const int h = blockIdx.y;
    const int bh = b * HH + h;

    s_s[t]  = g_asrc[bh * NN + t];
    s_pj[t] = t;
    s_dd[t] = g_adst[bh * NN + t];

    // bitonic sort ascending; j<=32 stages warp-local
    {
        int prev_cross = 1;
        for (int k = 2; k <= 512; k <<= 1) {
            for (int j = k >> 1; j > 0; j >>= 1) {
                int cross = (j >= 64);
                if (cross | prev_cross) __syncthreads(); else __syncwarp();
                if (t < 256) {
                    int i = ((t & ~(j - 1)) << 1) | (t & (j - 1));
                    int p = i | j;
                    bool up = ((i & k) == 0);
                    float ki = s_s[i], kp = s_s[p];
                    if (up ? (ki > kp) : (ki < kp)) {
                        s_s[i] = kp; s_s[p] = ki;
                        int tmp = s_pj[i]; s_pj[i] = s_pj[p]; s_pj[p] = tmp;
                    }
                }
                prev_cross = cross;
            }
        }
        __syncthreads();
    }

    // sorted weights + per-i split
    int k_reg;
    {
        float sv = s_s[t];
        s_W1[t] = __expf(sv);
        s_W2[t] = __expf(NEGS * sv);
        float thr = -s_dd[t];
        int lo = 0, hi = 512;
        while (lo < hi) {
            int mid = (lo + hi) >> 1;
            if (s_s[mid] < thr) lo = mid + 1; else hi = mid;
        }
        k_reg = lo;
    }
    __syncthreads();

    const float* hb = g_h + (size_t)bh * NN * CC;

    // chunk sums (float2 over h rows)
    #pragma unroll
    for (int p = t; p < 2048; p += 512) {
        int m = p >> 5, c = (p & 31) * 2;
        float2 f1 = make_float2(0.f, 0.f), f2 = make_float2(0.f, 0.f);
        #pragma unroll
        for (int r = 0; r < 8; r++) {
            int jj = m * 8 + r;
            float2 hv = *(const float2*)(hb + (size_t)s_pj[jj] * 64 + c);
            float w1 = s_W1[jj], w2 = s_W2[jj];
            f1.x += w1 * hv.x; f1.y += w1 * hv.y;
            f2.x += w2 * hv.x; f2.y += w2 * hv.y;
        }
        *(float2*)&CH1[m * 64 + c] = f1;
        *(float2*)&CH2[(m + 1) * 64 + c] = f2;
    }
    if (t < 64) {
        int m = t;
        float f1 = 0.f, f2 = 0.f;
        #pragma unroll
        for (int r = 0; r < 8; r++) { f1 += s_W1[m*8+r]; f2 += s_W2[m*8+r]; }
        CH1d[m] = f1;
        CH2d[m + 1] = f2;
    }
    __syncthreads();

    // chunk scans
    if (t < 64) {
        const int c = t;
        CH1[64 * 64 + c] = 0.f;
        CH2[c] = 0.f;
        float run = 0.f;
        for (int m = 63; m >= 0; m--) { run += CH1[m * 64 + c]; CH1[m * 64 + c] = run; }
        float run2 = 0.f;
        for (int m = 1; m <= 64; m++) { run2 += CH2[m * 64 + c]; CH2[m * 64 + c] = run2; }
    } else if (t == 64) {
        CH1d[64] = 0.f;
        float run = 0.f;
        for (int m = 63; m >= 0; m--) { run += CH1d[m]; CH1d[m] = run; }
    } else if (t == 65) {
        CH2d[0] = 0.f;
        float run = 0.f;
        for (int m = 1; m <= 64; m++) { run += CH2d[m]; CH2d[m] = run; }
    }
    __syncthreads();

    // full per-position arrays + scalar arrays
    {
        float* S1 = g_S1f + (size_t)bh * 520 * 64;
        float* P2 = g_P2f + (size_t)bh * 520 * 64;
        #pragma unroll
        for (int p = t; p < 2048; p += 512) {
            int m = p >> 5, c = (p & 31) * 2;
            float2 hv[8];
            #pragma unroll
            for (int r = 0; r < 8; r++)
                hv[r] = *(const float2*)(hb + (size_t)s_pj[m * 8 + r] * 64 + c);
            float2 run1 = *(const float2*)&CH1[(m + 1) * 64 + c];
            #pragma unroll
            for (int r = 7; r >= 0; r--) {
                float w = s_W1[m * 8 + r];
                run1.x += w * hv[r].x; run1.y += w * hv[r].y;
                *(float2*)&S1[(size_t)(m * 8 + r) * 64 + c] = run1;
            }
            float2 run2 = *(const float2*)&CH2[m * 64 + c];
            #pragma unroll
            for (int r = 0; r < 8; r++) {
                *(float2*)&P2[(size_t)(m * 8 + r) * 64 + c] = run2;
                float w = s_W2[m * 8 + r];
                run2.x += w * hv[r].x; run2.y += w * hv[r].y;
            }
        }
        if (t < 64) {
            int m = t;
            float run1 = CH1d[m + 1];
            #pragma unroll
            for (int r = 7; r >= 0; r--) { run1 += s_W1[m*8+r]; s1d[m*8+r] = run1; }
            float run2 = CH2d[m];
            #pragma unroll
            for (int r = 0; r < 8; r++) { p2d[m*8+r] = run2; run2 += s_W2[m*8+r]; }
        }
        if (t < 64) {
            S1[(size_t)512 * 64 + t] = 0.f;
            P2[(size_t)512 * 64 + t] = CH2[64 * 64 + t];
        }
        if (t == 64) { s1d[512] = 0.f; p2d[512] = CH2d[64]; }
    }
    __syncthreads();

    // per-i scalars
    {
        float dv = s_dd[t];
        float e1 = __expf(dv);
        float e2 = __expf(NEGS * dv);
        float den = e1 * s1d[k_reg] + e2 * p2d[k_reg];
        float inv = 0.25f * __frcp_rn(den);
        int gi = bh * NN + t;
        g_r1[gi] = e1 * inv;
        g_r2[gi] = e2 * inv;
        g_k[gi]  = k_reg;
    }
}

// ---------------------------------------------------------------------------
// k_emit (proven): x[b,i,c] =
//   relu( sum_h (r1*S1f[k_i][c] + r2*P2f[k_i][c]) + bias[c] )
// ---------------------------------------------------------------------------
__global__ __launch_bounds__(256) void k_emit(const float* __restrict__ cb)
{
    __shared__ float s_r1[4][64], s_r2[4][64];
    __shared__ int   s_kk[4][64];
    const int t  = threadIdx.x;
    const int b  = blockIdx.x;
    const int i0 = blockIdx.y * 64;

    {
        const int h = t >> 6, ii = t & 63;
        const int idx = (b * HH + h) * NN + i0 + ii;
        s_r1[h][ii] = g_r1[idx];
        s_r2[h][ii] = g_r2[idx];
        s_kk[h][ii] = g_k[idx];
    }
    __syncthreads();

    const int c  = t & 63;
    const int ig = t >> 6;
    const float bias = cb[c];
    const size_t hb0 = (size_t)(b * HH) * 520 * 64;

    for (int ii = ig; ii < 64; ii += 4) {
        float acc = bias;
        #pragma unroll
        for (int h = 0; h < HH; h++) {
            const size_t base = hb0 + ((size_t)h * 520 + s_kk[h][ii]) * 64 + c;
            acc += s_r1[h][ii] * g_S1f[base] + s_r2[h][ii] * g_P2f[base];
        }
        g_x[(size_t)(b * NN + i0 + ii) * DD + c] = fmaxf(acc, 0.f);
    }
}

// ---------------------------------------------------------------------------
// k_read: node-mean pooling + readout linear.
// ---------------------------------------------------------------------------
__global__ __launch_bounds__(256) void k_read(
    const float* __restrict__ rw, const float* __restrict__ rb,
    float* __restrict__ out)
{
    __shared__ float s_part[4][64];
    __shared__ float s_pool[64];
    const int t = threadIdx.x;
    const int b = blockIdx.x;
    const int c = t & 63, pg = t >> 6;
    float s = 0.f;
    for (int i = pg; i < NN; i += 4)
        s += g_x[(size_t)(b * NN + i) * DD + c];
    s_part[pg][c] = s;
    __syncthreads();
    if (t < 64)
        s_pool[t] = (s_part[0][t] + s_part[1][t] + s_part[2][t] + s_part[3][t])
                    * (1.0f / NN);
    __syncthreads();
    if (t < 64) {
        float a = rb[t];
        #pragma unroll 8
        for (int c2 = 0; c2 < 64; c2++)
            a += s_pool[c2] * rw[t * 64 + c2];
        out[b * 64 + t] = a;
    }
}

// ---------------------------------------------------------------------------
extern "C" void kernel_launch(void* const* d_in, const int* in_sizes, int n_in,
                              void* d_out, int out_size)
{
    const float* emb = (const float*)d_in[0];
    const float* lin = (const float*)d_in[1];
    const float* aS  = (const float*)d_in[2];
    const float* aD  = (const float*)d_in[3];
    const float* cb  = (const float*)d_in[4];
    const float* rw  = (const float*)d_in[5];
    const float* rb  = (const float*)d_in[6];
    float* out = (float*)d_out;

    float* gx = nullptr;
    cudaGetSymbolAddress((void**)&gx, g_x);

    const int LIN_SMEM  = 64 * 136 * 2 * 4;  // 69632 B
    const int PREP_SMEM = 12180 * 4;         // 48720 B
    cudaFuncSetAttribute(k_lin, cudaFuncAttributeMaxDynamicSharedMemorySize, LIN_SMEM);
    cudaFuncSetAttribute(k_prep, cudaFuncAttributeMaxDynamicSharedMemorySize, PREP_SMEM);

    for (int l = 0; l < 3; l++) {
        const float* xin = (l == 0) ? emb : gx;
        k_lin<<<dim3(256, 2), 256, LIN_SMEM>>>(xin, lin + l * 16384,
                                               aS + l * HH * CC, aD + l * HH * CC);
        k_prep<<<dim3(64, 4), 512, PREP_SMEM>>>();
        k_emit<<<dim3(64, 8), 256>>>(cb + l * CC);
    }
    k_read<<<64, 256>>>(rw, rb, out);
}

// round 15
// speedup vs baseline: 1.0340x; 1.0340x over previous
#include <cuda_runtime.h>
#include <cstdint>

#define BB 64
#define NN 512
#define DD 64
#define HH 4
#define CC 64
#define NEGS 0.2f

// Scratch (device globals - no runtime allocation allowed)
__device__ float g_h[BB*HH*NN*CC];       // [b][h][n][c]  (head-major slabs)
__device__ float g_x[BB*NN*DD];          // layer activations
__device__ float g_asrc[BB*HH*NN];       // [b][h][n]
__device__ float g_adst[BB*HH*NN];       // [b][h][n]
__device__ float g_part[BB*HH*NN*CC];    // per-head normalized aggregation

// ---------------------------------------------------------------------------
// k_lin (LOCKED R7 scalar): h = x @ W^T, 64x64 tile, one head per blockIdx.y,
// 256 threads, 4i x 4c microtile. Epilogue: h -> g_h[b][h][n][c] slab +
// a_src/a_dst via shfl reduce.
// ---------------------------------------------------------------------------
__global__ __launch_bounds__(256) void k_lin(
    const float* __restrict__ x, const float* __restrict__ W,
    const float* __restrict__ attS, const float* __restrict__ attD)
{
    __shared__ float s_x[64][68];   // transposed [k][row]
    __shared__ float s_w[64][68];   // transposed [k][col]
    const int t    = threadIdx.x;
    const int row0 = blockIdx.x * 64;
    const int hh   = blockIdx.y;

    {
        const int li = t >> 2;
        const int c4 = t & 3;
        const float4* x4 = (const float4*)x;
        const float4* w4 = (const float4*)W;
        #pragma unroll
        for (int q = 0; q < 4; q++) {
            int kc = c4 + q * 4;
            float4 v = x4[(row0 + li) * 16 + kc];
            s_x[kc*4+0][li] = v.x; s_x[kc*4+1][li] = v.y;
            s_x[kc*4+2][li] = v.z; s_x[kc*4+3][li] = v.w;
            float4 u = w4[(hh * 64 + li) * 16 + kc];
            s_w[kc*4+0][li] = u.x; s_w[kc*4+1][li] = u.y;
            s_w[kc*4+2][li] = u.z; s_w[kc*4+3][li] = u.w;
        }
    }
    __syncthreads();

    const int tx = t & 15, ty = t >> 4;
    float acc[4][4] = {};
    #pragma unroll
    for (int k = 0; k < 64; k++) {
        float4 a = *(const float4*)&s_x[k][ty * 4];
        float4 b = *(const float4*)&s_w[k][tx * 4];
        float av[4] = {a.x, a.y, a.z, a.w};
        float bv[4] = {b.x, b.y, b.z, b.w};
        #pragma unroll
        for (int i = 0; i < 4; i++)
            #pragma unroll
            for (int c = 0; c < 4; c++)
                acc[i][c] += av[i] * bv[c];
    }

    #pragma unroll
    for (int i = 0; i < 4; i++) {
        int ng = row0 + ty * 4 + i;
        int b = ng >> 9, n = ng & 511;
        *(float4*)&g_h[((size_t)(b * HH + hh) * NN + n) * CC + tx * 4] =
            make_float4(acc[i][0], acc[i][1], acc[i][2], acc[i][3]);
    }

    float aSv[4], aDv[4];
    #pragma unroll
    for (int c = 0; c < 4; c++) {
        aSv[c] = attS[hh * 64 + tx * 4 + c];
        aDv[c] = attD[hh * 64 + tx * 4 + c];
    }
    #pragma unroll
    for (int i = 0; i < 4; i++) {
        float ps = 0.f, pd = 0.f;
        #pragma unroll
        for (int c = 0; c < 4; c++) { ps += acc[i][c] * aSv[c]; pd += acc[i][c] * aDv[c]; }
        #pragma unroll
        for (int off = 8; off > 0; off >>= 1) {
            ps += __shfl_xor_sync(0xffffffffu, ps, off);
            pd += __shfl_xor_sync(0xffffffffu, pd, off);
        }
        if (tx == 0) {
            int ng = row0 + ty * 4 + i;
            int b = ng >> 9, n = ng & 511;
            g_asrc[(b * HH + hh) * NN + n] = ps;
            g_adst[(b * HH + hh) * NN + n] = pd;
        }
    }
}

// ---------------------------------------------------------------------------
// k_prep (v2: bucketed in-kernel emission), 512 threads, one block per (b,h).
// Sort s; chunk(8) sums + scans; counting-sort i's by split k_i; during the
// per-chunk scan pass, emit part[i][c] = r1_i*S1[j][c] + r2_i*P2[j][c] for
// every i in bucket j. No full suffix/prefix arrays written to global.
// ---------------------------------------------------------------------------
extern __shared__ float psm[];

__global__ __launch_bounds__(512) void k_prep()
{
    float* s_s   = psm;              // 512
    float* s_dd  = psm + 512;        // 512
    float* s_W1  = psm + 1024;       // 512
    float* s_W2  = psm + 1536;       // 512
    int*   s_pj  = (int*)(psm + 2048);   // 512
    float* CH1   = psm + 2560;       // [66][64]
    float* CH2   = psm + 6784;       // [66][64]
    float* CH1d  = psm + 11008;      // [66]
    float* CH2d  = psm + 11074;      // [66]
    float* s1d   = psm + 11140;      // [520]
    float* p2d   = psm + 11660;      // [520]
    float* r1s   = psm + 12180;      // [512]
    float* r2s   = psm + 12692;      // [512]
    int*   s_cnt = (int*)(psm + 13204);  // [513]
    int*   scA   = (int*)(psm + 13717);  // [513]
    int*   scB   = (int*)(psm + 14230);  // [513]
    int*   s_st  = (int*)(psm + 14743);  // [513]
    int*   s_ord = (int*)(psm + 15256);  // [512] -> 15768 words total

    const int t = threadIdx.x;
    const int b = blockIdx.x;
    const int h = blockIdx.y;
    const int bh = b * HH + h;

    // phase 1: load
    s_s[t]  = g_asrc[bh * NN + t];
    s_pj[t] = t;
    s_dd[t] = g_adst[bh * NN + t];

    // phase 2: bitonic sort ascending; j<=32 stages warp-local
    {
        int prev_cross = 1;
        for (int k = 2; k <= 512; k <<= 1) {
            for (int j = k >> 1; j > 0; j >>= 1) {
                int cross = (j >= 64);
                if (cross | prev_cross) __syncthreads(); else __syncwarp();
                if (t < 256) {
                    int i = ((t & ~(j - 1)) << 1) | (t & (j - 1));
                    int p = i | j;
                    bool up = ((i & k) == 0);
                    float ki = s_s[i], kp = s_s[p];
                    if (up ? (ki > kp) : (ki < kp)) {
                        s_s[i] = kp; s_s[p] = ki;
                        int tmp = s_pj[i]; s_pj[i] = s_pj[p]; s_pj[p] = tmp;
                    }
                }
                prev_cross = cross;
            }
        }
        __syncthreads();
    }

    // phase 3: sorted weights + per-i split
    int k_reg;
    {
        float sv = s_s[t];
        s_W1[t] = __expf(sv);
        s_W2[t] = __expf(NEGS * sv);
        float thr = -s_dd[t];
        int lo = 0, hi = 512;
        while (lo < hi) {
            int mid = (lo + hi) >> 1;
            if (s_s[mid] < thr) lo = mid + 1; else hi = mid;
        }
        k_reg = lo;
    }
    __syncthreads();

    const float* hb = g_h + (size_t)bh * NN * CC;

    // phase 4: chunk sums (float2 over h rows) + scalar chunk sums
    #pragma unroll
    for (int p = t; p < 2048; p += 512) {
        int m = p >> 5, c = (p & 31) * 2;
        float2 f1 = make_float2(0.f, 0.f), f2 = make_float2(0.f, 0.f);
        #pragma unroll
        for (int r = 0; r < 8; r++) {
            int jj = m * 8 + r;
            float2 hv = *(const float2*)(hb + (size_t)s_pj[jj] * 64 + c);
            float w1 = s_W1[jj], w2 = s_W2[jj];
            f1.x += w1 * hv.x; f1.y += w1 * hv.y;
            f2.x += w2 * hv.x; f2.y += w2 * hv.y;
        }
        *(float2*)&CH1[m * 64 + c] = f1;
        *(float2*)&CH2[(m + 1) * 64 + c] = f2;
    }
    if (t < 64) {
        int m = t;
        float f1 = 0.f, f2 = 0.f;
        #pragma unroll
        for (int r = 0; r < 8; r++) { f1 += s_W1[m*8+r]; f2 += s_W2[m*8+r]; }
        CH1d[m] = f1;
        CH2d[m + 1] = f2;
    }
    __syncthreads();

    // phase 5: chunk scans
    if (t < 64) {
        const int c = t;
        CH1[64 * 64 + c] = 0.f;
        CH2[c] = 0.f;
        float run = 0.f;
        for (int m = 63; m >= 0; m--) { run += CH1[m * 64 + c]; CH1[m * 64 + c] = run; }
        float run2 = 0.f;
        for (int m = 1; m <= 64; m++) { run2 += CH2[m * 64 + c]; CH2[m * 64 + c] = run2; }
    } else if (t == 64) {
        CH1d[64] = 0.f;
        float run = 0.f;
        for (int m = 63; m >= 0; m--) { run += CH1d[m]; CH1d[m] = run; }
    } else if (t == 65) {
        CH2d[0] = 0.f;
        float run = 0.f;
        for (int m = 1; m <= 64; m++) { run += CH2d[m]; CH2d[m] = run; }
    }
    __syncthreads();

    // phase 5b: scalar full arrays (t<66) ; zero bucket counts (t>=128)
    if (t < 64) {
        int m = t;
        float run1 = CH1d[m + 1];
        #pragma unroll
        for (int r = 7; r >= 0; r--) { run1 += s_W1[m*8+r]; s1d[m*8+r] = run1; }
        float run2 = CH2d[m];
        #pragma unroll
        for (int r = 0; r < 8; r++) { p2d[m*8+r] = run2; run2 += s_W2[m*8+r]; }
    } else if (t == 64) {
        s1d[512] = 0.f; p2d[512] = CH2d[64];
    } else if (t >= 128) {
        for (int q = t - 128; q < 513; q += 384) s_cnt[q] = 0;
    }
    __syncthreads();

    // phase 5c: bucket counts
    atomicAdd(&s_cnt[k_reg], 1);
    __syncthreads();

    // phase 5d: inclusive Hillis-Steele scan of cnt (513) via ping-pong
    {
        int* pA = scA; int* pB = scB;
        for (int q = t; q < 513; q += 512) pA[q] = s_cnt[q];
        __syncthreads();
        for (int st = 1; st < 513; st <<= 1) {
            for (int q = t; q < 513; q += 512) {
                int v = pA[q];
                if (q >= st) v += pA[q - st];
                pB[q] = v;
            }
            __syncthreads();
            int* tmp = pA; pA = pB; pB = tmp;
        }
        // start = exclusive prefix; pB doubles as scatter cursor
        for (int q = t; q < 513; q += 512) {
            int ex = pA[q] - s_cnt[q];
            s_st[q] = ex;
            pB[q]   = ex;
        }
        __syncthreads();
        int pos = atomicAdd(&pB[k_reg], 1);
        s_ord[pos] = t;
        // per-i scalars (s1d/p2d ready since 5b sync)
        float dv = s_dd[t];
        float e1 = __expf(dv);
        float e2 = __expf(NEGS * dv);
        float den = e1 * s1d[k_reg] + e2 * p2d[k_reg];
        float inv = 0.25f * __frcp_rn(den);
        r1s[t] = e1 * inv;
        r2s[t] = e2 * inv;
    }
    __syncthreads();

    // phase 6: scan sweep with fused bucket emission
    float* gp = g_part + (size_t)bh * NN * CC;
    #pragma unroll
    for (int p = t; p < 2048; p += 512) {
        int m = p >> 5, c = (p & 31) * 2;
        float2 hv[8];
        #pragma unroll
        for (int r = 0; r < 8; r++)
            hv[r] = *(const float2*)(hb + (size_t)s_pj[m * 8 + r] * 64 + c);
        // ascending prefix values P2[j] for this chunk
        float2 p2r[8];
        float2 run2 = *(const float2*)&CH2[m * 64 + c];
        #pragma unroll
        for (int r = 0; r < 8; r++) {
            p2r[r] = run2;
            float w = s_W2[m * 8 + r];
            run2.x += w * hv[r].x; run2.y += w * hv[r].y;
        }
        // descending suffix S1[j] with emission
        float2 run1 = *(const float2*)&CH1[(m + 1) * 64 + c];
        #pragma unroll
        for (int r = 7; r >= 0; r--) {
            int j = m * 8 + r;
            float w = s_W1[j];
            run1.x += w * hv[r].x; run1.y += w * hv[r].y;
            int st0 = s_st[j], en = st0 + s_cnt[j];
            for (int pp = st0; pp < en; pp++) {
                int i = s_ord[pp];
                float r1v = r1s[i], r2v = r2s[i];
                float2 o;
                o.x = r1v * run1.x + r2v * p2r[r].x;
                o.y = r1v * run1.y + r2v * p2r[r].y;
                *(float2*)&gp[(size_t)i * 64 + c] = o;
            }
        }
    }
    // bucket 512 (k_i == 512): S1 = 0, P2 = total prefix
    {
        int n512 = s_cnt[512], base = s_st[512];
        for (int q = t; q < n512 * 32; q += 512) {
            int e = q >> 5, c = (q & 31) * 2;
            int i = s_ord[base + e];
            float r2v = r2s[i];
            float2 o;
            o.x = r2v * CH2[64 * 64 + c];
            o.y = r2v * CH2[64 * 64 + c + 1];
            *(float2*)&gp[(size_t)i * 64 + c] = o;
        }
    }
}

// ---------------------------------------------------------------------------
// k_comb: x[b,i,c] = relu( sum_h part[b,h,i,c] + bias[c] )  (float4, coalesced)
// ---------------------------------------------------------------------------
__global__ __launch_bounds__(256) void k_comb(const float* __restrict__ cb)
{
    const int t  = threadIdx.x;
    const int b  = blockIdx.x;
    const int i0 = blockIdx.y * 64;
    const int tx = t & 15;          // c quad
    const int ty = t >> 4;          // i group (16)
    float4 bias4 = *(const float4*)(cb + tx * 4);

    for (int ii = ty; ii < 64; ii += 16) {
        size_t base = ((size_t)(b * HH) * NN + i0 + ii) * CC + tx * 4;
        float4 p0 = *(const float4*)(g_part + base);
        float4 p1 = *(const float4*)(g_part + base + (size_t)NN * CC);
        float4 p2 = *(const float4*)(g_part + base + (size_t)2 * NN * CC);
        float4 p3 = *(const float4*)(g_part + base + (size_t)3 * NN * CC);
        float4 v;
        v.x = fmaxf(p0.x + p1.x + p2.x + p3.x + bias4.x, 0.f);
        v.y = fmaxf(p0.y + p1.y + p2.y + p3.y + bias4.y, 0.f);
        v.z = fmaxf(p0.z + p1.z + p2.z + p3.z + bias4.z, 0.f);
        v.w = fmaxf(p0.w + p1.w + p2.w + p3.w + bias4.w, 0.f);
        *(float4*)&g_x[(size_t)(b * NN + i0 + ii) * DD + tx * 4] = v;
    }
}

// ---------------------------------------------------------------------------
// k_read_comb: head-combine + bias + relu + node-mean pooling + readout.
// ---------------------------------------------------------------------------
__global__ __launch_bounds__(256) void k_read_comb(
    const float* __restrict__ rw, const float* __restrict__ rb,
    const float* __restrict__ cb2, float* __restrict__ out)
{
    __shared__ float s_part[4][64];
    __shared__ float s_pool[64];
    const int t = threadIdx.x;
    const int b = blockIdx.x;
    const int c = t & 63, pg = t >> 6;
    const float bias = cb2[c];
    float s = 0.f;
    for (int i = pg; i < NN; i += 4) {
        size_t base = ((size_t)(b * HH) * NN + i) * CC + c;
        float v = g_part[base] + g_part[base + (size_t)NN * CC]
                + g_part[base + (size_t)2 * NN * CC]
                + g_part[base + (size_t)3 * NN * CC];
        s += fmaxf(v + bias, 0.f);
    }
    s_part[pg][c] = s;
    __syncthreads();
    if (t < 64)
        s_pool[t] = (s_part[0][t] + s_part[1][t] + s_part[2][t] + s_part[3][t])
                    * (1.0f / NN);
    __syncthreads();
    if (t < 64) {
        float a = rb[t];
        #pragma unroll 8
        for (int c2 = 0; c2 < 64; c2++)
            a += s_pool[c2] * rw[t * 64 + c2];
        out[b * 64 + t] = a;
    }
}

// ---------------------------------------------------------------------------
extern "C" void kernel_launch(void* const* d_in, const int* in_sizes, int n_in,
                              void* d_out, int out_size)
{
    const float* emb = (const float*)d_in[0];
    const float* lin = (const float*)d_in[1];
    const float* aS  = (const float*)d_in[2];
    const float* aD  = (const float*)d_in[3];
    const float* cb  = (const float*)d_in[4];
    const float* rw  = (const float*)d_in[5];
    const float* rb  = (const float*)d_in[6];
    float* out = (float*)d_out;

    float* gx = nullptr;
    cudaGetSymbolAddress((void**)&gx, g_x);

    const int PREP_SMEM = 15768 * 4;   // 63072 B
    cudaFuncSetAttribute(k_prep, cudaFuncAttributeMaxDynamicSharedMemorySize, PREP_SMEM);

    for (int l = 0; l < 3; l++) {
        const float* xin = (l == 0) ? emb : gx;
        k_lin<<<dim3(512, 4), 256>>>(xin, lin + l * 16384,
                                     aS + l * HH * CC, aD + l * HH * CC);
        k_prep<<<dim3(64, 4), 512, PREP_SMEM>>>();
        if (l < 2) k_comb<<<dim3(64, 8), 256>>>(cb + l * CC);
    }
    k_read_comb<<<64, 256>>>(rw, rb, cb + 2 * CC, out);
}